// round 7
// baseline (speedup 1.0000x reference)
#include <cuda_runtime.h>
#include <math.h>

typedef unsigned long long ull;

// ---------------- problem constants ----------------
#define Bn    4
#define CIN   21
#define HL    81
#define WL    81
#define HW    6561
#define HWO   104976
#define WOUTX 324
#define XPW   88
#define XPP   7304        // 83*88

#define OUT_V_OFF 8817984
#define OUT_G_OFF 9027936

// ---------------- scratch ----------------
__device__ float g_xpad[Bn * CIN * XPP];
__device__ float g_hidden[Bn * 96 * XPP];
__device__ float g_raw[Bn * 9 * HW];

// ---------------- packed fp32x2 helpers ----------------
__device__ __forceinline__ ull pkf2(float lo, float hi) {
    ull r; asm("mov.b64 %0, {%1,%2};" : "=l"(r) : "f"(lo), "f"(hi)); return r;
}
__device__ __forceinline__ void upkf2(ull v, float& lo, float& hi) {
    asm("mov.b64 {%0,%1}, %2;" : "=f"(lo), "=f"(hi) : "l"(v));
}
__device__ __forceinline__ void ffma2(ull& d, ull a, ull b) {
    asm("fma.rn.f32x2 %0, %1, %2, %0;" : "+l"(d) : "l"(a), "l"(b));
}
__device__ __forceinline__ ull hilo(ull a, ull b) {
    float al, ah, bl, bh; upkf2(a, al, ah); upkf2(b, bl, bh); return pkf2(ah, bl);
}

__device__ __forceinline__ float fast_tanh(float x) {
    const float e2 = __expf(2.0f * x);
    return 1.0f - __fdividef(2.0f, e2 + 1.0f);
}
__device__ __forceinline__ float fast_sigmoid(float x) {
    return __fdividef(1.0f, 1.0f + __expf(-x));
}

// ==========================================================================
// Kernel 0: build xpad (zero halo) + zero hidden halos.
// ==========================================================================
#define PAD_N1 (Bn * CIN * XPP)
#define PAD_N2 (Bn * 96 * 744)
__global__ void pad_kernel(const float* __restrict__ x)
{
    const int idx = blockIdx.x * 256 + threadIdx.x;
    if (idx < PAD_N1) {
        const int plane = idx / XPP;
        const int rem   = idx - plane * XPP;
        const int r     = rem / XPW;
        const int col   = rem - r * XPW;
        float v = 0.f;
        if (r >= 1 && r <= HL && col >= 1 && col <= WL)
            v = x[plane * HW + (r - 1) * WL + (col - 1)];
        g_xpad[idx] = v;
    } else if (idx < PAD_N1 + PAD_N2) {
        const int j2    = idx - PAD_N1;
        const int plane = j2 / 744;
        const int j     = j2 - plane * 744;
        int off;
        if (j < 88)       off = j;
        else if (j < 176) off = 82 * XPW + (j - 88);
        else {
            const int jj = j - 176;
            const int rr = 1 + jj / 7;
            const int cc = jj - (jj / 7) * 7;
            off = rr * XPW + ((cc == 0) ? 0 : 81 + cc);
        }
        g_hidden[plane * XPP + off] = 0.f;
    }
}

// ==========================================================================
// Kernel 1: conv1 (21 -> 96), ReLU. 3 rows x 4 px x 4 co per thread.
// Double-buffered staging, one sync per chunk: next chunk's LDG->STS
// issued before compute so L2 latency overlaps FFMA2.
// ==========================================================================
#define C1_F4 (3 * 29 * 22)    // 1914 float4 per chunk
__global__ __launch_bounds__(192) void conv1_kernel(
    const float* __restrict__ w1o, const float* __restrict__ b1o,
    const float* __restrict__ w1g, const float* __restrict__ b1g)
{
    __shared__ __align__(16) float sx[2][3 * 29 * XPW];   // 61.3 KB
    __shared__ ull sw2[4 * 189];

    const int tile = blockIdx.x;
    const int cg   = blockIdx.y;
    const int b    = blockIdx.z;
    const int r0   = tile * 27;
    const int tid  = threadIdx.x;

    for (int i = tid; i < 4 * 189; i += 192) {
        const int co = i / 189, j = i - co * 189;
        const int co_out = cg * 4 + co;
        const float w = (co_out < 48) ? w1o[co_out * 189 + j] : w1g[(co_out - 48) * 189 + j];
        sw2[i] = pkf2(w, w);
    }

    const bool active = tid < 189;
    const int trp = active ? (tid / 21) : 0;
    const int tc  = active ? ((tid - trp * 21) * 4) : 0;
    const int trp3 = trp * 3;
    const int nvalid = (tc == 80) ? 1 : 4;

    // stage chunk 0
    {
        const float4* src = (const float4*)g_xpad;
        for (int i = tid; i < C1_F4; i += 192) {
            const int c  = i / 638;
            const int rm = i - c * 638;
            const int lr = rm / 22;
            const int f4 = rm - lr * 22;
            ((float4*)sx[0])[(c * 29 + lr) * 22 + f4] =
                src[((b * CIN + c) * XPP + (r0 + lr) * XPW) / 4 + f4];
        }
    }
    __syncthreads();

    ull acc[4][3][2];
#pragma unroll
    for (int co = 0; co < 4; ++co)
#pragma unroll
        for (int r = 0; r < 3; ++r) { acc[co][r][0] = 0ULL; acc[co][r][1] = 0ULL; }

    for (int cc = 0; cc < 7; ++cc) {
        const int cur = cc & 1;
        // prefetch next chunk into the other buffer (overlaps with compute)
        if (cc < 6) {
            const float4* src = (const float4*)g_xpad;
#pragma unroll 2
            for (int i = tid; i < C1_F4; i += 192) {
                const int c  = i / 638;
                const int rm = i - c * 638;
                const int lr = rm / 22;
                const int f4 = rm - lr * 22;
                ((float4*)sx[cur ^ 1])[(c * 29 + lr) * 22 + f4] =
                    src[((b * CIN + (cc + 1) * 3 + c) * XPP + (r0 + lr) * XPW) / 4 + f4];
            }
        }

        if (active) {
#pragma unroll
            for (int c = 0; c < 3; ++c) {
                ull PA[5], PAB[5], PB[5], PBC[5], PC[5];
#pragma unroll
                for (int rr = 0; rr < 5; ++rr) {
                    const float* rp = &sx[cur][(c * 29 + trp3 + rr) * XPW + tc];
                    const ull A  = *(const ull*)rp;
                    const ull Bv = *(const ull*)(rp + 2);
                    const ull Cv = *(const ull*)(rp + 4);
                    PA[rr] = A; PB[rr] = Bv; PC[rr] = Cv;
                    PAB[rr] = hilo(A, Bv); PBC[rr] = hilo(Bv, Cv);
                }
                const int wb = (cc * 3 + c) * 9;
#pragma unroll
                for (int ky = 0; ky < 3; ++ky)
#pragma unroll
                    for (int kx = 0; kx < 3; ++kx)
#pragma unroll
                        for (int co = 0; co < 4; ++co) {
                            const ull w = sw2[co * 189 + wb + ky * 3 + kx];
#pragma unroll
                            for (int r = 0; r < 3; ++r) {
                                const int rw = r + ky;
                                ffma2(acc[co][r][0],
                                      kx == 0 ? PA[rw] : (kx == 1 ? PAB[rw] : PB[rw]), w);
                                ffma2(acc[co][r][1],
                                      kx == 0 ? PB[rw] : (kx == 1 ? PBC[rw] : PC[rw]), w);
                            }
                        }
            }
        }
        __syncthreads();
    }

    if (active) {
#pragma unroll
        for (int co = 0; co < 4; ++co) {
            const int co_out = cg * 4 + co;
            const float bias = (co_out < 48) ? b1o[co_out] : b1g[co_out - 48];
#pragma unroll
            for (int r = 0; r < 3; ++r) {
                const int orow = r0 + trp3 + r;
                float* dst = &g_hidden[(b * 96 + co_out) * XPP + (orow + 1) * XPW + tc + 1];
                float v[4];
                upkf2(acc[co][r][0], v[0], v[1]);
                upkf2(acc[co][r][1], v[2], v[3]);
#pragma unroll
                for (int p = 0; p < 4; ++p)
                    if (p < nvalid) dst[p] = fmaxf(v[p] + bias, 0.f);
            }
        }
    }
}

// ==========================================================================
// Kernel 2: conv2 heads. grid (81 rows, Bn); block 96 (84 active).
// Thread = 1 row x 4 px x ncos co. Cosets: {0,1,2},{3,4,5},{6,7},{8}.
// Stage 96 ch in 12 chunks of (4 o-ch + 4 g-ch), double-buffered.
// ==========================================================================
#define C2_F4 (8 * 3 * 22)     // 528 float4 per chunk
__global__ __launch_bounds__(96) void conv2_kernel(
    const float* __restrict__ w2o, const float* __restrict__ b2o,
    const float* __restrict__ w2g, const float* __restrict__ b2g,
    float* __restrict__ out)
{
    __shared__ __align__(16) float sx[2][8 * 3 * XPW];   // 16.9 KB
    __shared__ ull sw2[9 * 432];                          // 31.1 KB

    const int row = blockIdx.x;      // output row 0..80
    const int b   = blockIdx.y;
    const int tid = threadIdx.x;

    for (int i = tid; i < 9 * 432; i += 96) {
        const int co = i / 432, j = i - co * 432;
        const float w = (co < 8) ? w2o[co * 432 + j] : w2g[j];
        sw2[i] = pkf2(w, w);
    }

    const bool active = tid < 84;
    const int coset = active ? (tid / 21) : 0;          // 0..3
    const int strip = active ? (tid - coset * 21) : 0;
    const int tc    = strip * 4;
    const int nvalid = (tc == 80) ? 1 : 4;
    const int ncos   = (coset < 2) ? 3 : ((coset == 2) ? 2 : 1);
    const int cobase = (coset < 3) ? (coset * 3) : 8;
    const int srcoff = (coset == 3) ? 4 : 0;            // gate reads staged g-chs

    // stage chunk 0: channels o[0..3], g[48..51]; padded rows row..row+2
    {
        const float4* src = (const float4*)g_hidden;
        for (int i = tid; i < C2_F4; i += 96) {
            const int c  = i / 66;
            const int rm = i - c * 66;
            const int lr = rm / 22;
            const int f4 = rm - lr * 22;
            const int ch = (c < 4) ? c : (48 + c - 4);
            ((float4*)sx[0])[(c * 3 + lr) * 22 + f4] =
                src[((b * 96 + ch) * XPP + (row + lr) * XPW) / 4 + f4];
        }
    }
    __syncthreads();

    ull acc[3][2];
#pragma unroll
    for (int j = 0; j < 3; ++j) { acc[j][0] = 0ULL; acc[j][1] = 0ULL; }

    for (int cc = 0; cc < 12; ++cc) {
        const int cur = cc & 1;
        if (cc < 11) {
            const float4* src = (const float4*)g_hidden;
#pragma unroll 2
            for (int i = tid; i < C2_F4; i += 96) {
                const int c  = i / 66;
                const int rm = i - c * 66;
                const int lr = rm / 22;
                const int f4 = rm - lr * 22;
                const int ch = (c < 4) ? ((cc + 1) * 4 + c) : (48 + (cc + 1) * 4 + c - 4);
                ((float4*)sx[cur ^ 1])[(c * 3 + lr) * 22 + f4] =
                    src[((b * 96 + ch) * XPP + (row + lr) * XPW) / 4 + f4];
            }
        }

        if (active) {
#pragma unroll
            for (int c = 0; c < 4; ++c) {
                ull PA[3], PAB[3], PB[3], PBC[3], PC[3];
#pragma unroll
                for (int rr = 0; rr < 3; ++rr) {
                    const float* rp = &sx[cur][((srcoff + c) * 3 + rr) * XPW + tc];
                    const ull A  = *(const ull*)rp;
                    const ull Bv = *(const ull*)(rp + 2);
                    const ull Cv = *(const ull*)(rp + 4);
                    PA[rr] = A; PB[rr] = Bv; PC[rr] = Cv;
                    PAB[rr] = hilo(A, Bv); PBC[rr] = hilo(Bv, Cv);
                }
                const int chw = (cc * 4 + c) * 9;
#pragma unroll
                for (int j = 0; j < 3; ++j) {
                    if (j < ncos) {
                        const int wb = (cobase + j) * 432 + chw;
#pragma unroll
                        for (int ky = 0; ky < 3; ++ky)
#pragma unroll
                            for (int kx = 0; kx < 3; ++kx) {
                                const ull w = sw2[wb + ky * 3 + kx];
                                ffma2(acc[j][0], kx == 0 ? PA[ky] : (kx == 1 ? PAB[ky] : PB[ky]), w);
                                ffma2(acc[j][1], kx == 0 ? PB[ky] : (kx == 1 ? PBC[ky] : PC[ky]), w);
                            }
                    }
                }
            }
        }
        __syncthreads();
    }

    if (active) {
#pragma unroll
        for (int j = 0; j < 3; ++j) {
            if (j >= ncos) continue;
            const int co = cobase + j;
            const float bias = (co < 8) ? b2o[co] : b2g[0];
            float v[4];
            upkf2(acc[j][0], v[0], v[1]);
            upkf2(acc[j][1], v[2], v[3]);
#pragma unroll
            for (int p = 0; p < 4; ++p) {
                if (p >= nvalid) continue;
                const int pix = row * WL + tc + p;
                const float raw = v[p] + bias;
                if (co < 8) {
                    const float t = fast_tanh(raw);
                    g_raw[(b * 9 + co) * HW + pix] = t;
                    out[OUT_V_OFF + (b * 8 + co) * HW + pix] = t;
                } else {
                    g_raw[(b * 9 + 8) * HW + pix] = fast_sigmoid(raw);
                }
            }
        }
    }
}

// ==========================================================================
// Kernel 3 (fuse + upsample): per lowres pixel x 3-channel group.
// grid (26, 7, 4); block 256.
// ==========================================================================
__global__ __launch_bounds__(256) void upfuse_kernel(
    const float* __restrict__ x, const float* __restrict__ beta,
    float* __restrict__ out)
{
    const int pix = blockIdx.x * blockDim.x + threadIdx.x;
    if (pix >= HW) return;
    const int grp = blockIdx.y;      // 0..6, channels grp*3..grp*3+2
    const int b   = blockIdx.z;
    const int y = pix / WL, xx = pix - y * WL;

    // ---- mask construction ----
    const float* vr = g_raw + b * 9 * HW;
    const float p0 = vr[0 * HW + pix] - vr[4 * HW + pix];
    const float p1 = vr[1 * HW + pix] - vr[5 * HW + pix];
    const float p2 = vr[2 * HW + pix] - vr[6 * HW + pix];
    const float p3 = vr[3 * HW + pix] - vr[7 * HW + pix];
    const float g  = vr[8 * HW + pix];

    const float k00 = (p0 + p1 + p2) * 0.125f;
    const float k01 = (p1 + p2 + p3) * 0.125f;
    const float k02 = (-p0 + p2 + p3) * 0.125f;
    const float k10 = (p0 + p1 - p3) * 0.125f;

    float kb[9];
    kb[0] = k00;  kb[1] = k01;  kb[2] = k02;
    kb[3] = k10;  kb[4] = 2.5f; kb[5] = -k10;
    kb[6] = -k02; kb[7] = -k01; kb[8] = -k00;

    float mx = kb[0];
#pragma unroll
    for (int n = 1; n < 9; ++n) mx = fmaxf(mx, kb[n]);
    float e[9], se = 0.f;
#pragma unroll
    for (int n = 0; n < 9; ++n) { e[n] = __expf((kb[n] - mx) * 2.0f); se += e[n]; }
    const float inv_se = __fdividef(1.0f, se);

    const float mean = 2.5f / 9.0f;
    float sa = 0.f;
#pragma unroll
    for (int n = 0; n < 9; ++n) sa += fabsf(kb[n] - mean);
    const float hinv = __fdividef(1.0f, sa + 1e-8f);

    const float lam = 0.15f * (1.0f - g);
    const float tbg = tanhf(beta[0]) * g;
    const float oml = 1.0f - lam;

    float wm[9];
#pragma unroll
    for (int n = 0; n < 9; ++n) wm[n] = lam * e[n] * inv_se + tbg * (kb[n] - mean) * hinv;

    // ---- g_up (group 0 only) ----
    if (grp == 0) {
        const float4 gq = make_float4(g, g, g, g);
        float* gd = &out[OUT_G_OFF + b * HWO + (y * 4) * WOUTX + xx * 4];
#pragma unroll
        for (int jy = 0; jy < 4; ++jy) *(float4*)(gd + jy * WOUTX) = gq;
    }

    // ---- per-pixel bilinear weight vectors (3 taps, zero at unused) ----
    const float sc = 80.0f / 323.0f;
    float wx3[4][3];
#pragma unroll
    for (int j = 0; j < 4; ++j) {
        const float fx = (float)(xx * 4 + j) * sc;
        int ix = (int)fx; if (ix > WL - 2) ix = WL - 2;
        const float wx = fx - (float)ix;
        const bool lo = (ix != xx);
        wx3[j][0] = lo ? (1.f - wx) : 0.f;
        wx3[j][1] = lo ? wx : (1.f - wx);
        wx3[j][2] = lo ? 0.f : wx;
    }
    ull wxp[2][3];
#pragma unroll
    for (int p = 0; p < 2; ++p)
#pragma unroll
        for (int j = 0; j < 3; ++j)
            wxp[p][j] = pkf2(wx3[2 * p][j], wx3[2 * p + 1][j]);

    ull wyp[4][3];
#pragma unroll
    for (int j = 0; j < 4; ++j) {
        const float fy = (float)(y * 4 + j) * sc;
        int iy = (int)fy; if (iy > HL - 2) iy = HL - 2;
        const float wy = fy - (float)iy;
        const bool lo = (iy != y);
        const float w0 = oml * (lo ? (1.f - wy) : 0.f);
        const float w1 = oml * (lo ? wy : (1.f - wy));
        const float w2 = oml * (lo ? 0.f : wy);
        wyp[j][0] = pkf2(w0, w0);
        wyp[j][1] = pkf2(w1, w1);
        wyp[j][2] = pkf2(w2, w2);
    }

    const int ym = (y == 0) ? 1 : y - 1,   yp = (y == HL - 1) ? HL - 2 : y + 1;
    const int xm = (xx == 0) ? 1 : xx - 1, xp = (xx == WL - 1) ? WL - 2 : xx + 1;
    const int ry[3] = {ym, y, yp};
    const int rx[3] = {xm, xx, xp};

#pragma unroll
    for (int cl = 0; cl < 3; ++cl) {
        const int ci = grp * 3 + cl;
        const float* xb = x + (b * CIN + ci) * HW;

        float t[3][3];
#pragma unroll
        for (int i = 0; i < 3; ++i)
#pragma unroll
            for (int j = 0; j < 3; ++j)
                t[i][j] = xb[ry[i] * WL + rx[j]];

        float yc = 0.f;
#pragma unroll
        for (int i = 0; i < 3; ++i)
#pragma unroll
            for (int j = 0; j < 3; ++j)
                yc += t[i][j] * wm[i * 3 + j];
        const ull yc2 = pkf2(yc, yc);

        ull cvp[3][2];
#pragma unroll
        for (int i = 0; i < 3; ++i) { cvp[i][0] = 0ULL; cvp[i][1] = 0ULL; }
#pragma unroll
        for (int i = 0; i < 3; ++i)
#pragma unroll
            for (int j = 0; j < 3; ++j) {
                const ull td = pkf2(t[i][j], t[i][j]);
                ffma2(cvp[i][0], td, wxp[0][j]);
                ffma2(cvp[i][1], td, wxp[1][j]);
            }

        float* dst = &out[(b * CIN + ci) * HWO + (y * 4) * WOUTX + xx * 4];
#pragma unroll
        for (int jy = 0; jy < 4; ++jy) {
            ull r0 = yc2, r1 = yc2;
#pragma unroll
            for (int i = 0; i < 3; ++i) {
                ffma2(r0, cvp[i][0], wyp[jy][i]);
                ffma2(r1, cvp[i][1], wyp[jy][i]);
            }
            float o0, o1, o2, o3;
            upkf2(r0, o0, o1);
            upkf2(r1, o2, o3);
            *(float4*)(dst + jy * WOUTX) = make_float4(o0, o1, o2, o3);
        }
    }
}

// ==========================================================================
extern "C" void kernel_launch(void* const* d_in, const int* in_sizes, int n_in,
                              void* d_out, int out_size)
{
    const float* x    = (const float*)d_in[0];
    const float* w1o  = (const float*)d_in[1];
    const float* b1o  = (const float*)d_in[2];
    const float* w2o  = (const float*)d_in[3];
    const float* b2o  = (const float*)d_in[4];
    const float* w1g  = (const float*)d_in[5];
    const float* b1g  = (const float*)d_in[6];
    const float* w2g  = (const float*)d_in[7];
    const float* b2g  = (const float*)d_in[8];
    const float* beta = (const float*)d_in[9];
    float* out = (float*)d_out;

    pad_kernel<<<(PAD_N1 + PAD_N2 + 255) / 256, 256>>>(x);
    conv1_kernel<<<dim3(3, 24, Bn), 192>>>(w1o, b1o, w1g, b1g);
    conv2_kernel<<<dim3(81, Bn), 96>>>(w2o, b2o, w2g, b2g, out);
    upfuse_kernel<<<dim3(26, 7, Bn), 256>>>(x, beta, out);
}